// round 1
// baseline (speedup 1.0000x reference)
#include <cuda_runtime.h>
#include <cstdint>

#define IN_CH   64
#define OUT_CH  128
#define HW      128
#define IMG     (HW*HW)         // 16384
#define NB      16
#define KS      576             // IN_CH * 9
#define KW4     (KS/4)          // 144 words per row
#define M_TOTAL (NB*IMG)        // 262144

// ---------------- device scratch (static, no allocation) ----------------
__device__ unsigned int g_act9[KS];                   // act amax bits (needs zeroing)
__device__ float        g_scale[KS];
__device__ float        g_params[2];                  // [0]=s_x, [1]=s_x*s_w
__device__ unsigned int g_qw[OUT_CH*KW4];             // int8 weights, [o][k] packed 4/word
__device__ unsigned int g_cols[(size_t)M_TOTAL*KW4];  // int8 im2col cols, [m][k] packed

// ---------------- k0: zero the atomicMax target ----------------
__global__ void k_zero() {
    int t = threadIdx.x;
    if (t < KS) g_act9[t] = 0u;
}

// ---------------- k1: per-(c,kh,kw) activation amax over valid window ----------------
__global__ void k_act9(const float* __restrict__ in) {
    const float* p = in + (size_t)blockIdx.x * IMG;   // blockIdx = b*64 + c
    float loc[9];
#pragma unroll
    for (int i = 0; i < 9; i++) loc[i] = 0.f;

    for (int idx = threadIdx.x; idx < IMG; idx += blockDim.x) {
        int r = idx >> 7, c = idx & 127;
        float a = fabsf(p[idx]);
        bool rok[3] = { r <= 126, true, r >= 1 };     // kh = 0,1,2 valid row ranges
        bool cok[3] = { c <= 126, true, c >= 1 };     // kw
#pragma unroll
        for (int kh = 0; kh < 3; kh++)
#pragma unroll
            for (int kw = 0; kw < 3; kw++) {
                float v = (rok[kh] && cok[kw]) ? a : 0.f;
                loc[kh*3+kw] = fmaxf(loc[kh*3+kw], v);
            }
    }
#pragma unroll
    for (int i = 0; i < 9; i++)
        for (int o = 16; o > 0; o >>= 1)
            loc[i] = fmaxf(loc[i], __shfl_xor_sync(0xffffffffu, loc[i], o));

    __shared__ float sred[8][9];
    int wid = threadIdx.x >> 5, lane = threadIdx.x & 31;
    if (lane == 0)
        for (int i = 0; i < 9; i++) sred[wid][i] = loc[i];
    __syncthreads();
    if (threadIdx.x < 9) {
        float m = sred[0][threadIdx.x];
        for (int w = 1; w < 8; w++) m = fmaxf(m, sred[w][threadIdx.x]);
        int c = blockIdx.x & 63;
        atomicMax(&g_act9[c*9 + threadIdx.x], __float_as_uint(m));  // nonneg: uint order == float order
    }
}

// ---------------- k2: scales + amaxes + weight quantization (single block, 576 thr) ----------------
__global__ void k_scales(const float* __restrict__ w) {
    __shared__ float red[KS];
    int t = threadIdx.x;                               // 0..575 = k

    float wm = 0.f;
    for (int o = 0; o < OUT_CH; o++) wm = fmaxf(wm, fabsf(w[o*KS + t]));

    float a = __uint_as_float(g_act9[t]);
    float s = __fdiv_rn(sqrtf(a), sqrtf(wm));          // act^0.5 / w^0.5 (ALPHA=0.5)
    if (s == 0.f) s = 1.f;
    g_scale[t] = s;

    // x_amax = max_k fl(act_k / s_k)   (monotone division => column max carries through)
    red[t] = __fdiv_rn(a, s);
    __syncthreads();
    for (int st = 512; st > 0; st >>= 1) {
        if (t < st && t + st < KS) red[t] = fmaxf(red[t], red[t+st]);
        __syncthreads();
    }
    float xa = red[0];
    __syncthreads();

    // w_amax = max |fl(w * s_k)|
    float wq = 0.f;
    for (int o = 0; o < OUT_CH; o++) wq = fmaxf(wq, fabsf(w[o*KS + t] * s));
    red[t] = wq;
    __syncthreads();
    for (int st = 512; st > 0; st >>= 1) {
        if (t < st && t + st < KS) red[t] = fmaxf(red[t], red[t+st]);
        __syncthreads();
    }
    float wa = red[0];

    float sx = (xa > 0.f) ? __fdiv_rn(xa, 127.f) : 1.f;
    float sw = (wa > 0.f) ? __fdiv_rn(wa, 127.f) : 1.f;

    // quantize weights -> int8 (byte write into packed word buffer)
    unsigned char* qb = (unsigned char*)g_qw;
    for (int o = 0; o < OUT_CH; o++) {
        float v = w[o*KS + t] * s;
        float q = rintf(__fdiv_rn(v, sw));             // rintf == round-half-even == jnp.round
        q = fminf(fmaxf(q, -127.f), 127.f);
        qb[o*KS + t] = (unsigned char)(signed char)(int)q;
    }
    if (t == 0) { g_params[0] = sx; g_params[1] = sx * sw; }
}

// ---------------- k3: fused im2col + activation fake-quant -> int8 cols ----------------
__global__ void k_quantx(const float* __restrict__ in) {
    __shared__ float        ssc[KS];
    __shared__ int          soff[KS];
    __shared__ signed char  skw[KS];
    __shared__ unsigned char srok[KS];

    int bh = blockIdx.x;                               // b*128 + h
    int b = bh >> 7, h = bh & 127;

    for (int k = threadIdx.x; k < KS; k += blockDim.x) {
        int kc = k / 9;
        int r  = k - kc*9;
        int kh = r / 3, kw = r - kh*3;
        ssc[k]  = g_scale[k];
        soff[k] = kc*IMG + (kh-1)*HW + (kw-1);
        skw[k]  = (signed char)(kw - 1);
        int ih  = h + kh - 1;
        srok[k] = (ih >= 0 && ih < HW) ? 1 : 0;
    }
    __syncthreads();

    float sx = g_params[0];
    const float* pin = in + (size_t)b * (IN_CH*IMG) + (size_t)h * HW;
    int mrow0 = bh * HW;                               // base m for this (b,h)

    for (int idx = threadIdx.x; idx < HW*KW4; idx += blockDim.x) {
        int w = idx / KW4;
        int kword = idx - w*KW4;
        unsigned int pack = 0u;
#pragma unroll
        for (int e = 0; e < 4; e++) {
            int k = kword*4 + e;
            int iw = w + (int)skw[k];
            float x = 0.f;
            if (srok[k] && (unsigned)iw < (unsigned)HW) x = pin[soff[k] + w];
            // exact reference rounding chain: fl(fl(x/scale)/s_x)
            float q = rintf(__fdiv_rn(__fdiv_rn(x, ssc[k]), sx));
            q = fminf(fmaxf(q, -127.f), 127.f);
            pack |= ((unsigned int)(unsigned char)(signed char)(int)q) << (8*e);
        }
        g_cols[(size_t)(mrow0 + w)*KW4 + kword] = pack;
    }
}

// ---------------- k4: int8 GEMM via dp4a, smem-resident A/B, staged epilogue ----------------
#define BM 64
#define RS 146          // padded row stride in words (146 mod 32 = 18 -> conflict-free strided-16 access)
extern __shared__ int smem4[];

__global__ void __launch_bounds__(256, 2) k_gemm(float* __restrict__ out) {
    int* sA = smem4;                    // BM * RS words
    int* sB = smem4 + BM*RS;            // OUT_CH * RS words
    int m0 = blockIdx.x * BM;

    const int* gB = (const int*)g_qw;
    for (int idx = threadIdx.x; idx < OUT_CH*KW4; idx += 256) {
        int rr = idx / KW4, w = idx - rr*KW4;
        sB[rr*RS + w] = gB[idx];
    }
    const unsigned int* gA = g_cols;
    for (int idx = threadIdx.x; idx < BM*KW4; idx += 256) {
        int rr = idx / KW4, w = idx - rr*KW4;
        sA[rr*RS + w] = (int)gA[(size_t)(m0 + rr)*KW4 + w];
    }
    __syncthreads();

    int tx = threadIdx.x & 15;          // n = tx + 16*j
    int ty = threadIdx.x >> 4;          // m = m0 + ty + 16*i
    int acc[4][8];
#pragma unroll
    for (int i = 0; i < 4; i++)
#pragma unroll
        for (int j = 0; j < 8; j++) acc[i][j] = 0;

    const int* ap = sA + ty*RS;
    const int* bp = sB + tx*RS;
#pragma unroll 2
    for (int kk = 0; kk < KW4; kk++) {
        int a0 = ap[kk], a1 = ap[16*RS + kk], a2 = ap[32*RS + kk], a3 = ap[48*RS + kk];
        int bb[8];
#pragma unroll
        for (int j = 0; j < 8; j++) bb[j] = bp[(j*16)*RS + kk];
#pragma unroll
        for (int j = 0; j < 8; j++) {
            acc[0][j] = __dp4a(a0, bb[j], acc[0][j]);
            acc[1][j] = __dp4a(a1, bb[j], acc[1][j]);
            acc[2][j] = __dp4a(a2, bb[j], acc[2][j]);
            acc[3][j] = __dp4a(a3, bb[j], acc[3][j]);
        }
    }

    float sxsw = g_params[1];
    __syncthreads();                    // done reading sA/sB; reuse as float staging
    float* sC = (float*)smem4;          // 32 x 65 floats (padded vs bank conflicts)
    int bimg = m0 >> 14;                // m0 / IMG
    int l0   = m0 & 16383;

    for (int ch = 0; ch < 4; ch++) {    // 32 output channels per chunk
#pragma unroll
        for (int i = 0; i < 4; i++)
#pragma unroll
            for (int jj = 0; jj < 2; jj++) {
                int j = 2*ch + jj;
                int nloc = tx + 16*jj;
                sC[nloc*65 + ty + 16*i] = (float)acc[i][j] * sxsw;
            }
        __syncthreads();
#pragma unroll
        for (int r = 0; r < 8; r++) {
            int pos = r*256 + threadIdx.x;
            int nloc = pos >> 6, mm = pos & 63;      // consecutive tid -> consecutive l => coalesced
            out[(size_t)(bimg*OUT_CH + 32*ch + nloc)*IMG + l0 + mm] = sC[nloc*65 + mm];
        }
        __syncthreads();
    }
}

// ---------------- launcher ----------------
extern "C" void kernel_launch(void* const* d_in, const int* in_sizes, int n_in,
                              void* d_out, int out_size) {
    const float* in = (const float*)d_in[0];   // (16,64,128,128) f32
    const float* w  = (const float*)d_in[1];   // (128,64,3,3) f32
    float* out = (float*)d_out;                // (16,128,128,128) f32

    k_zero  <<<1, KS>>>();
    k_act9  <<<NB*IN_CH, 256>>>(in);
    k_scales<<<1, KS>>>(w);
    k_quantx<<<NB*HW, 256>>>(in);

    cudaFuncSetAttribute(k_gemm, cudaFuncAttributeMaxDynamicSharedMemorySize,
                         (BM + OUT_CH) * RS * 4);
    k_gemm  <<<M_TOTAL/BM, 256, (BM + OUT_CH) * RS * 4>>>(out);
}

// round 3
// speedup vs baseline: 1.0784x; 1.0784x over previous
#include <cuda_runtime.h>
#include <cstdint>

#define IN_CH   64
#define OUT_CH  128
#define HW      128
#define IMG     (HW*HW)         // 16384
#define NB      16
#define KS      576             // IN_CH * 9
#define KW4     (KS/4)          // 144 words per row
#define M_TOTAL (NB*IMG)        // 262144

// ---------------- device scratch (static, no allocation) ----------------
__device__ unsigned int g_act9[KS];                   // act amax bits (needs zeroing)
__device__ float        g_scale[KS];
__device__ float        g_recip[KS];                  // 1/(scale_k * s_x), double-accurate
__device__ float        g_params[2];                  // [0]=s_x, [1]=s_x*s_w
__device__ unsigned int g_qw[OUT_CH*KW4];             // int8 weights, [o][k] packed 4/word
__device__ unsigned int g_cols[(size_t)M_TOTAL*KW4];  // int8 im2col cols, [m][k] packed

// ---------------- k0: zero the atomicMax target ----------------
__global__ void k_zero() {
    int t = threadIdx.x;
    if (t < KS) g_act9[t] = 0u;
}

// ---------------- k1: per-(c,kh,kw) activation amax over valid window ----------------
__global__ void k_act9(const float* __restrict__ in) {
    const float* p = in + (size_t)blockIdx.x * IMG;   // blockIdx = b*64 + c
    float loc[9];
#pragma unroll
    for (int i = 0; i < 9; i++) loc[i] = 0.f;

    for (int idx = threadIdx.x; idx < IMG; idx += blockDim.x) {
        int r = idx >> 7, c = idx & 127;
        float a = fabsf(p[idx]);
        bool rok[3] = { r <= 126, true, r >= 1 };     // kh = 0,1,2 valid row ranges
        bool cok[3] = { c <= 126, true, c >= 1 };     // kw
#pragma unroll
        for (int kh = 0; kh < 3; kh++)
#pragma unroll
            for (int kw = 0; kw < 3; kw++) {
                float v = (rok[kh] && cok[kw]) ? a : 0.f;
                loc[kh*3+kw] = fmaxf(loc[kh*3+kw], v);
            }
    }
#pragma unroll
    for (int i = 0; i < 9; i++)
        for (int o = 16; o > 0; o >>= 1)
            loc[i] = fmaxf(loc[i], __shfl_xor_sync(0xffffffffu, loc[i], o));

    __shared__ float sred[8][9];
    int wid = threadIdx.x >> 5, lane = threadIdx.x & 31;
    if (lane == 0)
        for (int i = 0; i < 9; i++) sred[wid][i] = loc[i];
    __syncthreads();
    if (threadIdx.x < 9) {
        float m = sred[0][threadIdx.x];
        for (int w = 1; w < 8; w++) m = fmaxf(m, sred[w][threadIdx.x]);
        int c = blockIdx.x & 63;
        atomicMax(&g_act9[c*9 + threadIdx.x], __float_as_uint(m));  // nonneg: uint order == float order
    }
}

// ---------------- k2: scales + amaxes + weight quantization (single block, 576 thr) ----------------
__global__ void k_scales(const float* __restrict__ w) {
    __shared__ float red[KS];
    int t = threadIdx.x;                               // 0..575 = k

    float wm = 0.f;
    for (int o = 0; o < OUT_CH; o++) wm = fmaxf(wm, fabsf(w[o*KS + t]));

    float a = __uint_as_float(g_act9[t]);
    float s = __fdiv_rn(sqrtf(a), sqrtf(wm));          // act^0.5 / w^0.5 (ALPHA=0.5)
    if (s == 0.f) s = 1.f;
    g_scale[t] = s;

    // x_amax = max_k fl(act_k / s_k)   (monotone division => column max carries through)
    red[t] = __fdiv_rn(a, s);
    __syncthreads();
    for (int st = 512; st > 0; st >>= 1) {
        if (t < st && t + st < KS) red[t] = fmaxf(red[t], red[t+st]);
        __syncthreads();
    }
    float xa = red[0];
    __syncthreads();

    // w_amax = max |fl(w * s_k)|
    float wq = 0.f;
    for (int o = 0; o < OUT_CH; o++) wq = fmaxf(wq, fabsf(w[o*KS + t] * s));
    red[t] = wq;
    __syncthreads();
    for (int st = 512; st > 0; st >>= 1) {
        if (t < st && t + st < KS) red[t] = fmaxf(red[t], red[t+st]);
        __syncthreads();
    }
    float wa = red[0];

    float sx = (xa > 0.f) ? __fdiv_rn(xa, 127.f) : 1.f;
    float sw = (wa > 0.f) ? __fdiv_rn(wa, 127.f) : 1.f;

    // combined reciprocal for the activation quantization path (double-accurate)
    g_recip[t] = (float)(1.0 / ((double)s * (double)sx));

    // quantize weights -> int8 (byte write into packed word buffer); exact chain kept
    unsigned char* qb = (unsigned char*)g_qw;
    for (int o = 0; o < OUT_CH; o++) {
        float v = w[o*KS + t] * s;
        float q = rintf(__fdiv_rn(v, sw));             // rintf == round-half-even == jnp.round
        q = fminf(fmaxf(q, -127.f), 127.f);
        qb[o*KS + t] = (unsigned char)(signed char)(int)q;
    }
    if (t == 0) { g_params[0] = sx; g_params[1] = sx * sw; }
}

// ---------------- k3: fused im2col + activation fake-quant -> int8 cols ----------------
// One block per (b, h, channel-half). 32 channels x 3 rows x (128+halo) staged in smem
// with zero-filled halo; each thread owns one packed kword (4 fixed (c,kh,kw) slots:
// reciprocals + smem base offsets in registers) and marches across w.
#define PADW 132            // plane row stride in floats (132 % 32 = 4 -> bank spread)
#define QX_THREADS 288      // 72 kwords * 4 w-groups

extern __shared__ unsigned char smem_dyn[];

__global__ void __launch_bounds__(QX_THREADS) k_quantx(const float* __restrict__ in) {
    float* sIn = (float*)smem_dyn;                     // [32][3][PADW]
    int bx = blockIdx.x;
    int chalf = bx & 1;
    int h     = (bx >> 1) & 127;
    int b     = bx >> 8;
    int c0    = chalf * 32;

    // stage input slab: channels c0..c0+31, rows h-1..h+1, cols -1..128 (zero halo)
    const float* pb = in + ((size_t)b * IN_CH + c0) * IMG;
    for (int idx = threadIdx.x; idx < 32*3*130; idx += QX_THREADS) {
        int c   = idx / 390;
        int rem = idx - c * 390;
        int row = rem / 130;
        int pcol = rem - row * 130;
        int ih = h + row - 1;
        int iw = pcol - 1;
        float v = 0.f;
        if ((unsigned)ih < (unsigned)HW && (unsigned)iw < (unsigned)HW)
            v = pb[(size_t)c * IMG + ih * HW + iw];
        sIn[(c*3 + row) * PADW + pcol] = v;
    }
    __syncthreads();

    int kl = threadIdx.x % 72;       // local kword 0..71
    int wg = threadIdx.x / 72;       // w-group 0..3

    int   base[4];
    float R4[4];
#pragma unroll
    for (int e = 0; e < 4; e++) {
        int k_loc = 4*kl + e;                 // 0..287
        int c  = k_loc / 9;
        int r  = k_loc - 9*c;
        int kh = r / 3;
        int kw = r - 3*kh;
        base[e] = (c*3 + kh) * PADW + kw;     // reading col (w+kw-1) with +1 halo => +w+kw
        R4[e]   = g_recip[chalf*288 + k_loc];
    }

    size_t orow = (size_t)((b*HW + h) * HW) * KW4 + chalf*72 + kl;

#pragma unroll 4
    for (int w = wg; w < HW; w += 4) {
        unsigned int pack = 0u;
#pragma unroll
        for (int e = 0; e < 4; e++) {
            float t = sIn[base[e] + w] * R4[e];
            t = fminf(fmaxf(t, -127.f), 127.f);
            int q = __float2int_rn(t);
            pack |= ((unsigned int)(q & 0xff)) << (8*e);
        }
        g_cols[orow + (size_t)w * KW4] = pack;
    }
}

// ---------------- k4: int8 GEMM via dp4a, smem-resident A/B, staged epilogue ----------------
#define BM 64
#define RS 146          // padded row stride in words (146 mod 32 = 18 -> conflict-free strided-16 access)
extern __shared__ int smem4[];

__global__ void __launch_bounds__(256, 2) k_gemm(float* __restrict__ out) {
    int* sA = smem4;                    // BM * RS words
    int* sB = smem4 + BM*RS;            // OUT_CH * RS words
    int m0 = blockIdx.x * BM;

    const int* gB = (const int*)g_qw;
    for (int idx = threadIdx.x; idx < OUT_CH*KW4; idx += 256) {
        int rr = idx / KW4, w = idx - rr*KW4;
        sB[rr*RS + w] = gB[idx];
    }
    const unsigned int* gA = g_cols;
    for (int idx = threadIdx.x; idx < BM*KW4; idx += 256) {
        int rr = idx / KW4, w = idx - rr*KW4;
        sA[rr*RS + w] = (int)gA[(size_t)(m0 + rr)*KW4 + w];
    }
    __syncthreads();

    int tx = threadIdx.x & 15;          // n = tx + 16*j
    int ty = threadIdx.x >> 4;          // m = m0 + ty + 16*i
    int acc[4][8];
#pragma unroll
    for (int i = 0; i < 4; i++)
#pragma unroll
        for (int j = 0; j < 8; j++) acc[i][j] = 0;

    const int* ap = sA + ty*RS;
    const int* bp = sB + tx*RS;
#pragma unroll 2
    for (int kk = 0; kk < KW4; kk++) {
        int a0 = ap[kk], a1 = ap[16*RS + kk], a2 = ap[32*RS + kk], a3 = ap[48*RS + kk];
        int bb[8];
#pragma unroll
        for (int j = 0; j < 8; j++) bb[j] = bp[(j*16)*RS + kk];
#pragma unroll
        for (int j = 0; j < 8; j++) {
            acc[0][j] = __dp4a(a0, bb[j], acc[0][j]);
            acc[1][j] = __dp4a(a1, bb[j], acc[1][j]);
            acc[2][j] = __dp4a(a2, bb[j], acc[2][j]);
            acc[3][j] = __dp4a(a3, bb[j], acc[3][j]);
        }
    }

    float sxsw = g_params[1];
    __syncthreads();                    // done reading sA/sB; reuse as float staging
    float* sC = (float*)smem4;          // 32 x 65 floats (padded vs bank conflicts)
    int bimg = m0 >> 14;                // m0 / IMG
    int l0   = m0 & 16383;

    for (int ch = 0; ch < 4; ch++) {    // 32 output channels per chunk
#pragma unroll
        for (int i = 0; i < 4; i++)
#pragma unroll
            for (int jj = 0; jj < 2; jj++) {
                int j = 2*ch + jj;
                int nloc = tx + 16*jj;
                sC[nloc*65 + ty + 16*i] = (float)acc[i][j] * sxsw;
            }
        __syncthreads();
#pragma unroll
        for (int r = 0; r < 8; r++) {
            int pos = r*256 + threadIdx.x;
            int nloc = pos >> 6, mm = pos & 63;      // consecutive tid -> consecutive l => coalesced
            out[(size_t)(bimg*OUT_CH + 32*ch + nloc)*IMG + l0 + mm] = sC[nloc*65 + mm];
        }
        __syncthreads();
    }
}

// ---------------- launcher ----------------
extern "C" void kernel_launch(void* const* d_in, const int* in_sizes, int n_in,
                              void* d_out, int out_size) {
    const float* in = (const float*)d_in[0];   // (16,64,128,128) f32
    const float* w  = (const float*)d_in[1];   // (128,64,3,3) f32
    float* out = (float*)d_out;                // (16,128,128,128) f32

    k_zero  <<<1, KS>>>();
    k_act9  <<<NB*IN_CH, 256>>>(in);
    k_scales<<<1, KS>>>(w);

    cudaFuncSetAttribute(k_quantx, cudaFuncAttributeMaxDynamicSharedMemorySize,
                         32*3*PADW*4);
    k_quantx<<<NB*HW*2, QX_THREADS, 32*3*PADW*4>>>(in);

    cudaFuncSetAttribute(k_gemm, cudaFuncAttributeMaxDynamicSharedMemorySize,
                         (BM + OUT_CH) * RS * 4);
    k_gemm  <<<M_TOTAL/BM, 256, (BM + OUT_CH) * RS * 4>>>(out);
}

// round 7
// speedup vs baseline: 1.4654x; 1.3589x over previous
#include <cuda_runtime.h>
#include <cstdint>

#define IN_CH   64
#define OUT_CH  128
#define HW      128
#define IMG     (HW*HW)         // 16384
#define NB      16
#define KS      576             // IN_CH * 9
#define KW4     (KS/4)          // 144 words per row
#define M_TOTAL (NB*IMG)        // 262144

// ---------------- device scratch (static, no allocation) ----------------
__device__ unsigned int g_act9[KS];
__device__ float        g_scale[KS];
__device__ float        g_recip[KS];
__device__ float        g_params[2];                  // [0]=s_x, [1]=s_x*s_w
__device__ unsigned int g_qw[OUT_CH*KW4];             // int8 weights [o][k] packed
__device__ unsigned int g_cols[(size_t)M_TOTAL*KW4];  // int8 im2col cols [m][k] packed

// ---------------- k0: zero the atomicMax target ----------------
__global__ void k_zero() {
    int t = threadIdx.x;
    if (t < KS) g_act9[t] = 0u;
}

// ---------------- k1: per-(c,kh,kw) activation amax over valid window ----------------
__global__ void k_act9(const float* __restrict__ in) {
    const float* p = in + (size_t)blockIdx.x * IMG;   // blockIdx = b*64 + c
    float loc[9];
#pragma unroll
    for (int i = 0; i < 9; i++) loc[i] = 0.f;

    for (int idx = threadIdx.x; idx < IMG; idx += blockDim.x) {
        int r = idx >> 7, c = idx & 127;
        float a = fabsf(p[idx]);
        bool rok[3] = { r <= 126, true, r >= 1 };
        bool cok[3] = { c <= 126, true, c >= 1 };
#pragma unroll
        for (int kh = 0; kh < 3; kh++)
#pragma unroll
            for (int kw = 0; kw < 3; kw++) {
                float v = (rok[kh] && cok[kw]) ? a : 0.f;
                loc[kh*3+kw] = fmaxf(loc[kh*3+kw], v);
            }
    }
#pragma unroll
    for (int i = 0; i < 9; i++)
        for (int o = 16; o > 0; o >>= 1)
            loc[i] = fmaxf(loc[i], __shfl_xor_sync(0xffffffffu, loc[i], o));

    __shared__ float sred[8][9];
    int wid = threadIdx.x >> 5, lane = threadIdx.x & 31;
    if (lane == 0)
        for (int i = 0; i < 9; i++) sred[wid][i] = loc[i];
    __syncthreads();
    if (threadIdx.x < 9) {
        float m = sred[0][threadIdx.x];
        for (int w = 1; w < 8; w++) m = fmaxf(m, sred[w][threadIdx.x]);
        int c = blockIdx.x & 63;
        atomicMax(&g_act9[c*9 + threadIdx.x], __float_as_uint(m));
    }
}

// ---------------- k2: scales + amaxes + weight quantization ----------------
__global__ void k_scales(const float* __restrict__ w) {
    __shared__ float red[KS];
    int t = threadIdx.x;

    float wm = 0.f;
    for (int o = 0; o < OUT_CH; o++) wm = fmaxf(wm, fabsf(w[o*KS + t]));

    float a = __uint_as_float(g_act9[t]);
    float s = __fdiv_rn(sqrtf(a), sqrtf(wm));
    if (s == 0.f) s = 1.f;
    g_scale[t] = s;

    red[t] = __fdiv_rn(a, s);
    __syncthreads();
    for (int st = 512; st > 0; st >>= 1) {
        if (t < st && t + st < KS) red[t] = fmaxf(red[t], red[t+st]);
        __syncthreads();
    }
    float xa = red[0];
    __syncthreads();

    float wq = 0.f;
    for (int o = 0; o < OUT_CH; o++) wq = fmaxf(wq, fabsf(w[o*KS + t] * s));
    red[t] = wq;
    __syncthreads();
    for (int st = 512; st > 0; st >>= 1) {
        if (t < st && t + st < KS) red[t] = fmaxf(red[t], red[t+st]);
        __syncthreads();
    }
    float wa = red[0];

    float sx = (xa > 0.f) ? __fdiv_rn(xa, 127.f) : 1.f;
    float sw = (wa > 0.f) ? __fdiv_rn(wa, 127.f) : 1.f;

    g_recip[t] = (float)(1.0 / ((double)s * (double)sx));

    unsigned char* qb = (unsigned char*)g_qw;
    for (int o = 0; o < OUT_CH; o++) {
        float v = w[o*KS + t] * s;
        float q = rintf(__fdiv_rn(v, sw));
        q = fminf(fmaxf(q, -127.f), 127.f);
        qb[o*KS + t] = (unsigned char)(signed char)(int)q;
    }
    if (t == 0) { g_params[0] = sx; g_params[1] = sx * sw; }
}

// ---------------- k3: fused im2col + activation fake-quant -> int8 cols ----------------
#define PADW 132
#define QX_THREADS 288

extern __shared__ unsigned char smem_dyn[];

__global__ void __launch_bounds__(QX_THREADS) k_quantx(const float* __restrict__ in) {
    float* sIn = (float*)smem_dyn;                     // [32][3][PADW]
    int bx = blockIdx.x;
    int chalf = bx & 1;
    int h     = (bx >> 1) & 127;
    int b     = bx >> 8;
    int c0    = chalf * 32;

    const float* pb = in + ((size_t)b * IN_CH + c0) * IMG;
    for (int idx = threadIdx.x; idx < 32*3*130; idx += QX_THREADS) {
        int c   = idx / 390;
        int rem = idx - c * 390;
        int row = rem / 130;
        int pcol = rem - row * 130;
        int ih = h + row - 1;
        int iw = pcol - 1;
        float v = 0.f;
        if ((unsigned)ih < (unsigned)HW && (unsigned)iw < (unsigned)HW)
            v = pb[(size_t)c * IMG + ih * HW + iw];
        sIn[(c*3 + row) * PADW + pcol] = v;
    }
    __syncthreads();

    int kl = threadIdx.x % 72;
    int wg = threadIdx.x / 72;

    int   base[4];
    float R4[4];
#pragma unroll
    for (int e = 0; e < 4; e++) {
        int k_loc = 4*kl + e;
        int c  = k_loc / 9;
        int r  = k_loc - 9*c;
        int kh = r / 3;
        int kw = r - 3*kh;
        base[e] = (c*3 + kh) * PADW + kw;
        R4[e]   = g_recip[chalf*288 + k_loc];
    }

    size_t orow = (size_t)((b*HW + h) * HW) * KW4 + chalf*72 + kl;

#pragma unroll 4
    for (int w = wg; w < HW; w += 4) {
        unsigned int pack = 0u;
#pragma unroll
        for (int e = 0; e < 4; e++) {
            float t = sIn[base[e] + w] * R4[e];
            t = fminf(fmaxf(t, -127.f), 127.f);
            int q = __float2int_rn(t);
            pack |= ((unsigned int)(q & 0xff)) << (8*e);
        }
        g_cols[orow + (size_t)w * KW4] = pack;
    }
}

// ---------------- k4: int8 GEMM via mma.sync m16n8k32 (tensor core, base-target PTX) ----------------
// Per CTA: BM=128, BN=128, K=576, A/B fully SMEM-resident. 8 warps = 2(m) x 4(n),
// each warp 64x32 via 4x4 m16n8k32 tiles. Row stride 592B (word stride 148, 148%32=20:
// fragment loads row*148 + tg hit 32 distinct banks).
#define BM 128
#define ASTRIDE 592
#define SMEM_B_OFF (128*ASTRIDE)                      // 75776
#define SMEM_GEMM_TOTAL (2*128*ASTRIDE)               // 151552

__device__ __forceinline__ void mma_i8(int* c, const int* a, const int* b) {
    asm volatile(
        "mma.sync.aligned.m16n8k32.row.col.s32.s8.s8.s32 "
        "{%0,%1,%2,%3}, {%4,%5,%6,%7}, {%8,%9}, {%0,%1,%2,%3};"
        : "+r"(c[0]), "+r"(c[1]), "+r"(c[2]), "+r"(c[3])
        : "r"(a[0]), "r"(a[1]), "r"(a[2]), "r"(a[3]), "r"(b[0]), "r"(b[1]));
}

extern __shared__ unsigned char smg[];

__global__ void __launch_bounds__(256, 1) k_gemm(float* __restrict__ out) {
    int tid = threadIdx.x;
    int wid = tid >> 5, lane = tid & 31;
    int wm = wid >> 2, wn = wid & 3;       // warp tile: rows wm*64.., cols wn*32..
    int g  = lane >> 2, tg = lane & 3;     // groupID / threadInGroup
    int m0 = blockIdx.x * BM;

    // stage A rows [m0, m0+128): 36 uint4 per row -> stride 592
    const uint4* gA = (const uint4*)g_cols;
    for (int idx = tid; idx < 128*36; idx += 256) {
        int row = idx / 36, j = idx - row*36;
        uint4 v = gA[(size_t)(m0 + row)*36 + j];
        *(uint4*)(smg + row*ASTRIDE + j*16) = v;
    }
    // stage B (weights, 128 rows x 576B)
    const uint4* gB = (const uint4*)g_qw;
    for (int idx = tid; idx < 128*36; idx += 256) {
        int row = idx / 36, j = idx - row*36;
        uint4 v = gB[(size_t)row*36 + j];
        *(uint4*)(smg + SMEM_B_OFF + row*ASTRIDE + j*16) = v;
    }
    __syncthreads();

    int acc[4][4][4];
#pragma unroll
    for (int i = 0; i < 4; i++)
#pragma unroll
        for (int j = 0; j < 4; j++)
#pragma unroll
            for (int r = 0; r < 4; r++) acc[i][j][r] = 0;

    const unsigned char* aB = smg + (wm*64 + g)*ASTRIDE + tg*4;
    const unsigned char* bB = smg + SMEM_B_OFF + (wn*32 + g)*ASTRIDE + tg*4;

#pragma unroll 2
    for (int kk = 0; kk < 18; kk++) {
        int ko = kk*32;
        int a[4][4];
#pragma unroll
        for (int i = 0; i < 4; i++) {
            const unsigned char* p = aB + i*16*ASTRIDE + ko;
            a[i][0] = *(const int*)(p);
            a[i][1] = *(const int*)(p + 8*ASTRIDE);
            a[i][2] = *(const int*)(p + 16);
            a[i][3] = *(const int*)(p + 8*ASTRIDE + 16);
        }
        int b[4][2];
#pragma unroll
        for (int j = 0; j < 4; j++) {
            const unsigned char* p = bB + j*8*ASTRIDE + ko;
            b[j][0] = *(const int*)(p);
            b[j][1] = *(const int*)(p + 16);
        }
#pragma unroll
        for (int i = 0; i < 4; i++)
#pragma unroll
            for (int j = 0; j < 4; j++)
                mma_i8(acc[i][j], a[i], b[j]);
    }

    float sxsw = g_params[1];
    __syncthreads();                       // done with sA/sB; reuse as f32 staging
    float* sC = (float*)smg;               // 32 x 132 floats
    int bimg = m0 >> 14;
    int l0   = m0 & 16383;

    for (int ch = 0; ch < 4; ch++) {       // 32 output channels per chunk
        if (wn == ch) {
#pragma unroll
            for (int i = 0; i < 4; i++)
#pragma unroll
                for (int j = 0; j < 4; j++) {
#pragma unroll
                    for (int dm = 0; dm < 2; dm++)
#pragma unroll
                        for (int dn = 0; dn < 2; dn++) {
                            int nloc = j*8 + tg*2 + dn;
                            int mloc = wm*64 + i*16 + g + dm*8;
                            sC[nloc*132 + mloc] = (float)acc[i][j][dm*2 + dn] * sxsw;
                        }
                }
        }
        __syncthreads();
#pragma unroll
        for (int r = 0; r < 16; r++) {
            int pos = r*256 + tid;
            int nl = pos >> 7, mm = pos & 127;   // consecutive tid -> consecutive l => coalesced
            out[(size_t)(bimg*OUT_CH + ch*32 + nl)*IMG + l0 + mm] = sC[nl*132 + mm];
        }
        __syncthreads();
    }
}

// ---------------- launcher ----------------
extern "C" void kernel_launch(void* const* d_in, const int* in_sizes, int n_in,
                              void* d_out, int out_size) {
    const float* in = (const float*)d_in[0];   // (16,64,128,128) f32
    const float* w  = (const float*)d_in[1];   // (128,64,3,3) f32
    float* out = (float*)d_out;                // (16,128,128,128) f32

    k_zero  <<<1, KS>>>();
    k_act9  <<<NB*IN_CH, 256>>>(in);
    k_scales<<<1, KS>>>(w);

    cudaFuncSetAttribute(k_quantx, cudaFuncAttributeMaxDynamicSharedMemorySize,
                         32*3*PADW*4);
    k_quantx<<<NB*HW*2, QX_THREADS, 32*3*PADW*4>>>(in);

    cudaFuncSetAttribute(k_gemm, cudaFuncAttributeMaxDynamicSharedMemorySize,
                         SMEM_GEMM_TOTAL);
    k_gemm  <<<M_TOTAL/BM, 256, SMEM_GEMM_TOTAL>>>(out);
}

// round 8
// speedup vs baseline: 2.1717x; 1.4820x over previous
#include <cuda_runtime.h>
#include <cstdint>

#define IN_CH   64
#define OUT_CH  128
#define HW      128
#define IMG     (HW*HW)         // 16384
#define NB      16
#define KS      576             // IN_CH * 9
#define KW4     (KS/4)          // 144 words per row
#define M_TOTAL (NB*IMG)        // 262144

// ---------------- device scratch (static, no allocation) ----------------
__device__ unsigned int g_act9[KS];
__device__ float        g_scale[KS];
__device__ float        g_recip[KS];
__device__ float        g_params[2];                  // [0]=s_x, [1]=s_x*s_w
__device__ unsigned int g_qw[OUT_CH*KW4];             // int8 weights [o][k] packed
__device__ unsigned int g_cols[(size_t)M_TOTAL*KW4];  // int8 im2col cols [m][k] packed

__device__ __forceinline__ unsigned smem_u32(const void* p) {
    unsigned a;
    asm("{ .reg .u64 t; cvta.to.shared.u64 t, %1; cvt.u32.u64 %0, t; }" : "=r"(a) : "l"(p));
    return a;
}
__device__ __forceinline__ void cp_async16(unsigned dst, const void* src) {
    asm volatile("cp.async.cg.shared.global [%0], [%1], 16;" :: "r"(dst), "l"(src) : "memory");
}

// ---------------- k0: zero the atomicMax target ----------------
__global__ void k_zero() {
    int t = threadIdx.x;
    if (t < KS) g_act9[t] = 0u;
}

// ---------------- k1: per-(c,kh,kw) activation amax over valid window ----------------
__global__ void k_act9(const float* __restrict__ in) {
    const float* p = in + (size_t)blockIdx.x * IMG;   // blockIdx = b*64 + c
    float loc[9];
#pragma unroll
    for (int i = 0; i < 9; i++) loc[i] = 0.f;

    for (int idx = threadIdx.x; idx < IMG; idx += blockDim.x) {
        int r = idx >> 7, c = idx & 127;
        float a = fabsf(p[idx]);
        bool rok[3] = { r <= 126, true, r >= 1 };
        bool cok[3] = { c <= 126, true, c >= 1 };
#pragma unroll
        for (int kh = 0; kh < 3; kh++)
#pragma unroll
            for (int kw = 0; kw < 3; kw++) {
                float v = (rok[kh] && cok[kw]) ? a : 0.f;
                loc[kh*3+kw] = fmaxf(loc[kh*3+kw], v);
            }
    }
#pragma unroll
    for (int i = 0; i < 9; i++)
        for (int o = 16; o > 0; o >>= 1)
            loc[i] = fmaxf(loc[i], __shfl_xor_sync(0xffffffffu, loc[i], o));

    __shared__ float sred[8][9];
    int wid = threadIdx.x >> 5, lane = threadIdx.x & 31;
    if (lane == 0)
        for (int i = 0; i < 9; i++) sred[wid][i] = loc[i];
    __syncthreads();
    if (threadIdx.x < 9) {
        float m = sred[0][threadIdx.x];
        for (int w = 1; w < 8; w++) m = fmaxf(m, sred[w][threadIdx.x]);
        int c = blockIdx.x & 63;
        atomicMax(&g_act9[c*9 + threadIdx.x], __float_as_uint(m));
    }
}

// ---------------- k2: scales + amaxes + weight quantization ----------------
__global__ void k_scales(const float* __restrict__ w) {
    __shared__ float red[KS];
    int t = threadIdx.x;

    float wm = 0.f;
    for (int o = 0; o < OUT_CH; o++) wm = fmaxf(wm, fabsf(w[o*KS + t]));

    float a = __uint_as_float(g_act9[t]);
    float s = __fdiv_rn(sqrtf(a), sqrtf(wm));
    if (s == 0.f) s = 1.f;
    g_scale[t] = s;

    red[t] = __fdiv_rn(a, s);
    __syncthreads();
    for (int st = 512; st > 0; st >>= 1) {
        if (t < st && t + st < KS) red[t] = fmaxf(red[t], red[t+st]);
        __syncthreads();
    }
    float xa = red[0];
    __syncthreads();

    float wq = 0.f;
    for (int o = 0; o < OUT_CH; o++) wq = fmaxf(wq, fabsf(w[o*KS + t] * s));
    red[t] = wq;
    __syncthreads();
    for (int st = 512; st > 0; st >>= 1) {
        if (t < st && t + st < KS) red[t] = fmaxf(red[t], red[t+st]);
        __syncthreads();
    }
    float wa = red[0];

    float sx = (xa > 0.f) ? __fdiv_rn(xa, 127.f) : 1.f;
    float sw = (wa > 0.f) ? __fdiv_rn(wa, 127.f) : 1.f;

    g_recip[t] = (float)(1.0 / ((double)s * (double)sx));

    unsigned char* qb = (unsigned char*)g_qw;
    for (int o = 0; o < OUT_CH; o++) {
        float v = w[o*KS + t] * s;
        float q = rintf(__fdiv_rn(v, sw));
        q = fminf(fmaxf(q, -127.f), 127.f);
        qb[o*KS + t] = (unsigned char)(signed char)(int)q;
    }
    if (t == 0) { g_params[0] = sx; g_params[1] = sx * sw; }
}

// ---------------- k3: fused im2col + activation fake-quant -> int8 cols ----------------
#define PADW 132
#define QX_THREADS 288

extern __shared__ unsigned char smem_dyn[];

__global__ void __launch_bounds__(QX_THREADS) k_quantx(const float* __restrict__ in) {
    float* sIn = (float*)smem_dyn;                     // [32][3][PADW]
    int bx = blockIdx.x;
    int chalf = bx & 1;
    int h     = (bx >> 1) & 127;
    int b     = bx >> 8;
    int c0    = chalf * 32;

    const float* pb = in + ((size_t)b * IN_CH + c0) * IMG;
    for (int idx = threadIdx.x; idx < 32*3*130; idx += QX_THREADS) {
        int c   = idx / 390;
        int rem = idx - c * 390;
        int row = rem / 130;
        int pcol = rem - row * 130;
        int ih = h + row - 1;
        int iw = pcol - 1;
        float v = 0.f;
        if ((unsigned)ih < (unsigned)HW && (unsigned)iw < (unsigned)HW)
            v = pb[(size_t)c * IMG + ih * HW + iw];
        sIn[(c*3 + row) * PADW + pcol] = v;
    }
    __syncthreads();

    int kl = threadIdx.x % 72;
    int wg = threadIdx.x / 72;

    int   base[4];
    float R4[4];
#pragma unroll
    for (int e = 0; e < 4; e++) {
        int k_loc = 4*kl + e;
        int c  = k_loc / 9;
        int r  = k_loc - 9*c;
        int kh = r / 3;
        int kw = r - 3*kh;
        base[e] = (c*3 + kh) * PADW + kw;
        R4[e]   = g_recip[chalf*288 + k_loc];
    }

    size_t orow = (size_t)((b*HW + h) * HW) * KW4 + chalf*72 + kl;

#pragma unroll 4
    for (int w = wg; w < HW; w += 4) {
        unsigned int pack = 0u;
#pragma unroll
        for (int e = 0; e < 4; e++) {
            float t = sIn[base[e] + w] * R4[e];
            t = fminf(fmaxf(t, -127.f), 127.f);
            int q = __float2int_rn(t);
            pack |= ((unsigned int)(q & 0xff)) << (8*e);
        }
        g_cols[orow + (size_t)w * KW4] = pack;
    }
}

// ---------------- k4: int8 GEMM via mma.sync m16n8k32, 2 CTAs/SM ----------------
// BM=64, BN=128, K=576 resident. 8 warps = 2(m) x 4(n), each warp 32x32 via
// 2x4 m16n8k32 tiles. smem/CTA = 113.7KB -> 2 CTAs/SM (16 warps) for
// staging/compute overlap across CTAs. cp.async staging.
#define BM 64
#define ASTRIDE 592
#define SMEM_B_OFF (BM*ASTRIDE)                       // 37888
#define SMEM_GEMM_TOTAL (SMEM_B_OFF + 128*ASTRIDE)    // 113664

__device__ __forceinline__ void mma_i8(int* c, const int* a, const int* b) {
    asm volatile(
        "mma.sync.aligned.m16n8k32.row.col.s32.s8.s8.s32 "
        "{%0,%1,%2,%3}, {%4,%5,%6,%7}, {%8,%9}, {%0,%1,%2,%3};"
        : "+r"(c[0]), "+r"(c[1]), "+r"(c[2]), "+r"(c[3])
        : "r"(a[0]), "r"(a[1]), "r"(a[2]), "r"(a[3]), "r"(b[0]), "r"(b[1]));
}

extern __shared__ unsigned char smg[];

__global__ void __launch_bounds__(256, 2) k_gemm(float* __restrict__ out) {
    int tid = threadIdx.x;
    int wid = tid >> 5, lane = tid & 31;
    int wm = wid >> 2, wn = wid & 3;       // warp tile: rows wm*32.., cols wn*32..
    int g  = lane >> 2, tg = lane & 3;     // groupID / threadInGroup
    int m0 = blockIdx.x * BM;
    unsigned sbase = smem_u32(smg);

    // stage A rows [m0, m0+64): 36 uint4 per row, cp.async
    const uint4* gA = (const uint4*)g_cols;
    for (int idx = tid; idx < BM*36; idx += 256) {
        int row = idx / 36, j = idx - row*36;
        cp_async16(sbase + row*ASTRIDE + j*16, gA + (size_t)(m0 + row)*36 + j);
    }
    // stage B (weights, 128 rows x 576B)
    const uint4* gB = (const uint4*)g_qw;
    for (int idx = tid; idx < 128*36; idx += 256) {
        int row = idx / 36, j = idx - row*36;
        cp_async16(sbase + SMEM_B_OFF + row*ASTRIDE + j*16, gB + (size_t)row*36 + j);
    }
    asm volatile("cp.async.commit_group;" ::: "memory");
    asm volatile("cp.async.wait_group 0;" ::: "memory");
    __syncthreads();

    int acc[2][4][4];
#pragma unroll
    for (int i = 0; i < 2; i++)
#pragma unroll
        for (int j = 0; j < 4; j++)
#pragma unroll
            for (int r = 0; r < 4; r++) acc[i][j][r] = 0;

    const unsigned char* aB = smg + (wm*32 + g)*ASTRIDE + tg*4;
    const unsigned char* bB = smg + SMEM_B_OFF + (wn*32 + g)*ASTRIDE + tg*4;

#pragma unroll 3
    for (int kk = 0; kk < 18; kk++) {
        int ko = kk*32;
        int a[2][4];
#pragma unroll
        for (int i = 0; i < 2; i++) {
            const unsigned char* p = aB + i*16*ASTRIDE + ko;
            a[i][0] = *(const int*)(p);
            a[i][1] = *(const int*)(p + 8*ASTRIDE);
            a[i][2] = *(const int*)(p + 16);
            a[i][3] = *(const int*)(p + 8*ASTRIDE + 16);
        }
        int b[4][2];
#pragma unroll
        for (int j = 0; j < 4; j++) {
            const unsigned char* p = bB + j*8*ASTRIDE + ko;
            b[j][0] = *(const int*)(p);
            b[j][1] = *(const int*)(p + 16);
        }
#pragma unroll
        for (int i = 0; i < 2; i++)
#pragma unroll
            for (int j = 0; j < 4; j++)
                mma_i8(acc[i][j], a[i], b[j]);
    }

    float sxsw = g_params[1];
    __syncthreads();                       // done with sA/sB; reuse as f32 staging
    float* sC = (float*)smg;               // 32 x 68 floats per chunk
    int bimg = m0 >> 14;
    int l0   = m0 & 16383;

    for (int ch = 0; ch < 4; ch++) {       // 32 output channels per chunk
        if (wn == ch) {
#pragma unroll
            for (int i = 0; i < 2; i++)
#pragma unroll
                for (int j = 0; j < 4; j++) {
#pragma unroll
                    for (int dm = 0; dm < 2; dm++)
#pragma unroll
                        for (int dn = 0; dn < 2; dn++) {
                            int nloc = j*8 + tg*2 + dn;
                            int mloc = wm*32 + i*16 + g + dm*8;
                            sC[nloc*68 + mloc] = (float)acc[i][j][dm*2 + dn] * sxsw;
                        }
                }
        }
        __syncthreads();
#pragma unroll
        for (int r = 0; r < 8; r++) {
            int pos = r*256 + tid;
            int nl = pos >> 6, mm = pos & 63;    // consecutive tid -> consecutive l => coalesced
            out[(size_t)(bimg*OUT_CH + ch*32 + nl)*IMG + l0 + mm] = sC[nl*68 + mm];
        }
        __syncthreads();
    }
}

// ---------------- launcher ----------------
extern "C" void kernel_launch(void* const* d_in, const int* in_sizes, int n_in,
                              void* d_out, int out_size) {
    const float* in = (const float*)d_in[0];   // (16,64,128,128) f32
    const float* w  = (const float*)d_in[1];   // (128,64,3,3) f32
    float* out = (float*)d_out;                // (16,128,128,128) f32

    k_zero  <<<1, KS>>>();
    k_act9  <<<NB*IN_CH, 256>>>(in);
    k_scales<<<1, KS>>>(w);

    cudaFuncSetAttribute(k_quantx, cudaFuncAttributeMaxDynamicSharedMemorySize,
                         32*3*PADW*4);
    k_quantx<<<NB*HW*2, QX_THREADS, 32*3*PADW*4>>>(in);

    cudaFuncSetAttribute(k_gemm, cudaFuncAttributeMaxDynamicSharedMemorySize,
                         SMEM_GEMM_TOTAL);
    k_gemm  <<<M_TOTAL/BM, 256, SMEM_GEMM_TOTAL>>>(out);
}

// round 13
// speedup vs baseline: 2.3314x; 1.0735x over previous
#include <cuda_runtime.h>
#include <cstdint>

#define IN_CH   64
#define OUT_CH  128
#define HW      128
#define IMG     (HW*HW)         // 16384
#define NB      16
#define KS      576             // IN_CH * 9
#define KW4     (KS/4)          // 144 words per row
#define M_TOTAL (NB*IMG)        // 262144

// ---------------- device scratch (static, no allocation) ----------------
__device__ unsigned int g_act9[KS];
__device__ float        g_scale[KS];
__device__ float        g_recip[KS];
__device__ float        g_params[2];                  // [0]=s_x, [1]=s_x*s_w
__device__ unsigned int g_qw[OUT_CH*KW4];             // int8 weights [o][k] packed

// ---------------- k0: zero the atomicMax target ----------------
__global__ void k_zero() {
    int t = threadIdx.x;
    if (t < KS) g_act9[t] = 0u;
}

// ---------------- k1: per-(c,kh,kw) activation amax over valid window ----------------
__global__ void k_act9(const float* __restrict__ in) {
    const float* p = in + (size_t)blockIdx.x * IMG;   // blockIdx = b*64 + c
    float loc[9];
#pragma unroll
    for (int i = 0; i < 9; i++) loc[i] = 0.f;

    for (int idx = threadIdx.x; idx < IMG; idx += blockDim.x) {
        int r = idx >> 7, c = idx & 127;
        float a = fabsf(p[idx]);
        bool rok[3] = { r <= 126, true, r >= 1 };
        bool cok[3] = { c <= 126, true, c >= 1 };
#pragma unroll
        for (int kh = 0; kh < 3; kh++)
#pragma unroll
            for (int kw = 0; kw < 3; kw++) {
                float v = (rok[kh] && cok[kw]) ? a : 0.f;
                loc[kh*3+kw] = fmaxf(loc[kh*3+kw], v);
            }
    }
#pragma unroll
    for (int i = 0; i < 9; i++)
        for (int o = 16; o > 0; o >>= 1)
            loc[i] = fmaxf(loc[i], __shfl_xor_sync(0xffffffffu, loc[i], o));

    __shared__ float sred[8][9];
    int wid = threadIdx.x >> 5, lane = threadIdx.x & 31;
    if (lane == 0)
        for (int i = 0; i < 9; i++) sred[wid][i] = loc[i];
    __syncthreads();
    if (threadIdx.x < 9) {
        float m = sred[0][threadIdx.x];
        for (int w = 1; w < 8; w++) m = fmaxf(m, sred[w][threadIdx.x]);
        int c = blockIdx.x & 63;
        atomicMax(&g_act9[c*9 + threadIdx.x], __float_as_uint(m));
    }
}

// ---------------- k2: scales + amaxes + weight quantization ----------------
__global__ void k_scales(const float* __restrict__ w) {
    __shared__ float red[KS];
    int t = threadIdx.x;

    float wm = 0.f;
    for (int o = 0; o < OUT_CH; o++) wm = fmaxf(wm, fabsf(w[o*KS + t]));

    float a = __uint_as_float(g_act9[t]);
    float s = __fdiv_rn(sqrtf(a), sqrtf(wm));
    if (s == 0.f) s = 1.f;
    g_scale[t] = s;

    red[t] = __fdiv_rn(a, s);
    __syncthreads();
    for (int st = 512; st > 0; st >>= 1) {
        if (t < st && t + st < KS) red[t] = fmaxf(red[t], red[t+st]);
        __syncthreads();
    }
    float xa = red[0];
    __syncthreads();

    float wq = 0.f;
    for (int o = 0; o < OUT_CH; o++) wq = fmaxf(wq, fabsf(w[o*KS + t] * s));
    red[t] = wq;
    __syncthreads();
    for (int st = 512; st > 0; st >>= 1) {
        if (t < st && t + st < KS) red[t] = fmaxf(red[t], red[t+st]);
        __syncthreads();
    }
    float wa = red[0];

    float sx = (xa > 0.f) ? __fdiv_rn(xa, 127.f) : 1.f;
    float sw = (wa > 0.f) ? __fdiv_rn(wa, 127.f) : 1.f;

    g_recip[t] = (float)(1.0 / ((double)s * (double)sx));

    unsigned char* qb = (unsigned char*)g_qw;
    for (int o = 0; o < OUT_CH; o++) {
        float v = w[o*KS + t] * s;
        float q = rintf(__fdiv_rn(v, sw));
        q = fminf(fmaxf(q, -127.f), 127.f);
        qb[o*KS + t] = (unsigned char)(signed char)(int)q;
    }
    if (t == 0) { g_params[0] = sx; g_params[1] = sx * sw; }
}

// ---------------- k3: FUSED quantize + int8 GEMM (mma.sync m16n8k32, 2 CTAs/SM) ----------------
// BM=64, BN=128, K=576 resident. No async copies anywhere: B staged with plain
// LDG.128 -> STS.128 (weights L2-hot), A tile quantized in-kernel from the raw
// input (zero-init covers all padding). Mainloop/epilogue identical to the
// proven round-8 kernel. smem = 113,664B -> 2 CTAs/SM.
#define BM 64
#define ASTRIDE 592
#define SMEM_B_OFF (BM*ASTRIDE)                       // 37888
#define SMEM_GEMM_TOTAL (SMEM_B_OFF + 128*ASTRIDE)    // 113664

__device__ __forceinline__ void mma_i8(int* c, const int* a, const int* b) {
    asm volatile(
        "mma.sync.aligned.m16n8k32.row.col.s32.s8.s8.s32 "
        "{%0,%1,%2,%3}, {%4,%5,%6,%7}, {%8,%9}, {%0,%1,%2,%3};"
        : "+r"(c[0]), "+r"(c[1]), "+r"(c[2]), "+r"(c[3])
        : "r"(a[0]), "r"(a[1]), "r"(a[2]), "r"(a[3]), "r"(b[0]), "r"(b[1]));
}

extern __shared__ unsigned char smg[];

__global__ void __launch_bounds__(256, 2) k_gemm(const float* __restrict__ in,
                                                 float* __restrict__ out) {
    int tid = threadIdx.x;
    int wid = tid >> 5, lane = tid & 31;
    int wm = wid >> 2, wn = wid & 3;       // warp tile: rows wm*32.., cols wn*32..
    int g  = lane >> 2, tg = lane & 3;     // groupID / threadInGroup
    int m0 = blockIdx.x * BM;
    int b  = m0 >> 14;                     // batch
    int h  = (m0 >> 7) & 127;              // image row
    int w0 = m0 & 127;                     // 0 or 64
    (void)smg;

    // ---- stage B (weights, 128 rows x 576B): plain LDG.128 -> STS.128 ----
    const uint4* gB = (const uint4*)g_qw;
    for (int idx = tid; idx < 128*36; idx += 256) {
        int row = idx / 36, j = idx - row*36;
        *(uint4*)(smg + SMEM_B_OFF + row*ASTRIDE + j*16) = gB[(size_t)row*36 + j];
    }

    // ---- zero-init A region (covers all padding cases) ----
    for (int idx = tid; idx < BM*37; idx += 256)
        *(uint4*)(smg + idx*16) = make_uint4(0,0,0,0);
    __syncthreads();

    // ---- build A: load input float4 chunks, quantize, scatter bytes ----
    // planes: (c in 0..63, r in 0..2), each 18 aligned float4 chunks covering
    // absolute cols [w0-4, w0+68). Chunks fully in [0,128) or fully out.
    for (int idx = tid; idx < 192*18; idx += 256) {
        int plane = idx / 18;
        int i     = idx - plane*18;
        int c     = plane / 3;
        int r     = plane - 3*c;
        int ih    = h + r - 1;
        int col0  = w0 - 4 + i*4;
        bool ok = ((unsigned)ih < (unsigned)HW) && (col0 >= 0) && (col0 < HW);
        if (ok) {
            float4 x = *(const float4*)(in + ((size_t)(b*IN_CH + c)*HW + ih)*HW + col0);
            int kbase = c*9 + r*3;
            float R0 = g_recip[kbase + 0];
            float R1 = g_recip[kbase + 1];
            float R2 = g_recip[kbase + 2];
            float xv[4] = {x.x, x.y, x.z, x.w};
            float Rk[3] = {R0, R1, R2};
#pragma unroll
            for (int e = 0; e < 4; e++) {
                int wlb = col0 + e - w0 + 1;          // wl for kw=0
#pragma unroll
                for (int kw = 0; kw < 3; kw++) {
                    int wl = wlb - kw;
                    if ((unsigned)wl < (unsigned)BM) {
                        float t = xv[e] * Rk[kw];
                        t = fminf(fmaxf(t, -127.f), 127.f);
                        int q = __float2int_rn(t);
                        smg[wl*ASTRIDE + kbase + kw] = (unsigned char)(signed char)q;
                    }
                }
            }
        }
    }
    __syncthreads();

    // ---- int8 MMA mainloop (identical to round-8) ----
    int acc[2][4][4];
#pragma unroll
    for (int i = 0; i < 2; i++)
#pragma unroll
        for (int j = 0; j < 4; j++)
#pragma unroll
            for (int r = 0; r < 4; r++) acc[i][j][r] = 0;

    const unsigned char* aB = smg + (wm*32 + g)*ASTRIDE + tg*4;
    const unsigned char* bB = smg + SMEM_B_OFF + (wn*32 + g)*ASTRIDE + tg*4;

#pragma unroll 3
    for (int kk = 0; kk < 18; kk++) {
        int ko = kk*32;
        int a[2][4];
#pragma unroll
        for (int i = 0; i < 2; i++) {
            const unsigned char* p = aB + i*16*ASTRIDE + ko;
            a[i][0] = *(const int*)(p);
            a[i][1] = *(const int*)(p + 8*ASTRIDE);
            a[i][2] = *(const int*)(p + 16);
            a[i][3] = *(const int*)(p + 8*ASTRIDE + 16);
        }
        int bb[4][2];
#pragma unroll
        for (int j = 0; j < 4; j++) {
            const unsigned char* p = bB + j*8*ASTRIDE + ko;
            bb[j][0] = *(const int*)(p);
            bb[j][1] = *(const int*)(p + 16);
        }
#pragma unroll
        for (int i = 0; i < 2; i++)
#pragma unroll
            for (int j = 0; j < 4; j++)
                mma_i8(acc[i][j], a[i], bb[j]);
    }

    // ---- epilogue: smem transpose stage -> coalesced stores ----
    float sxsw = g_params[1];
    __syncthreads();                       // done with sA/sB; reuse as f32 staging
    float* sC = (float*)smg;               // 32 x 68 floats per chunk
    int l0 = m0 & 16383;

    for (int ch = 0; ch < 4; ch++) {       // 32 output channels per chunk
        if (wn == ch) {
#pragma unroll
            for (int i = 0; i < 2; i++)
#pragma unroll
                for (int j = 0; j < 4; j++) {
#pragma unroll
                    for (int dm = 0; dm < 2; dm++)
#pragma unroll
                        for (int dn = 0; dn < 2; dn++) {
                            int nloc = j*8 + tg*2 + dn;
                            int mloc = wm*32 + i*16 + g + dm*8;
                            sC[nloc*68 + mloc] = (float)acc[i][j][dm*2 + dn] * sxsw;
                        }
                }
        }
        __syncthreads();
#pragma unroll
        for (int r = 0; r < 8; r++) {
            int pos = r*256 + tid;
            int nl = pos >> 6, mm = pos & 63;    // consecutive tid -> consecutive l => coalesced
            out[(size_t)(b*OUT_CH + ch*32 + nl)*IMG + l0 + mm] = sC[nl*68 + mm];
        }
        __syncthreads();
    }
}

// ---------------- launcher ----------------
extern "C" void kernel_launch(void* const* d_in, const int* in_sizes, int n_in,
                              void* d_out, int out_size) {
    const float* in = (const float*)d_in[0];   // (16,64,128,128) f32
    const float* w  = (const float*)d_in[1];   // (128,64,3,3) f32
    float* out = (float*)d_out;                // (16,128,128,128) f32

    k_zero  <<<1, KS>>>();
    k_act9  <<<NB*IN_CH, 256>>>(in);
    k_scales<<<1, KS>>>(w);

    cudaFuncSetAttribute(k_gemm, cudaFuncAttributeMaxDynamicSharedMemorySize,
                         SMEM_GEMM_TOTAL);
    k_gemm  <<<M_TOTAL/BM, 256, SMEM_GEMM_TOTAL>>>(in, out);
}